// round 5
// baseline (speedup 1.0000x reference)
#include <cuda_runtime.h>
#include <math.h>

#define BB 512
#define CC 256
#define NW 8                 // 256 concepts / 32 bits
#define TEMP_INV (1.0f/0.07f)
#define GRID BB

// ---- persistent scratch (no allocation allowed) ----
__device__ float    g_clip[2*BB];    // per-row (lse - diag): img [0..511], txt [512..1023]
__device__ float    g_ccl [2*BB];    // per-row bce sum [0..511], mask sum [512..1023]
__device__ float    g_kl  [BB];      // per-row KL term
__device__ unsigned g_bits[BB*NW];   // binary concept bitmasks (row-major [row][word])
__device__ int      g_cnt [BB];      // per-row positive-concept popcount
__device__ unsigned g_count = 0;     // barrier-1 arrivals (RED), reset by block 0 at end
__device__ unsigned g_fin   = 0;     // barrier-2 arrivals (RED), reset by block 0 at end

// ---------- deterministic fused block reductions (256 threads) ----------
__device__ __forceinline__ void blockSum3(float& a, float& b, float& c) {
    __shared__ float sh[3][8];
    int tid = threadIdx.x;
    #pragma unroll
    for (int o = 16; o > 0; o >>= 1) {
        a += __shfl_down_sync(0xffffffffu, a, o);
        b += __shfl_down_sync(0xffffffffu, b, o);
        c += __shfl_down_sync(0xffffffffu, c, o);
    }
    __syncthreads();
    if ((tid & 31) == 0) { int w = tid >> 5; sh[0][w] = a; sh[1][w] = b; sh[2][w] = c; }
    __syncthreads();
    float ra = 0.f, rb = 0.f, rc = 0.f;
    #pragma unroll
    for (int w = 0; w < 8; w++) { ra += sh[0][w]; rb += sh[1][w]; rc += sh[2][w]; }
    a = ra; b = rb; c = rc;
}

__device__ __forceinline__ void blockSum2(float& a, float& b) {
    __shared__ float sh[2][8];
    int tid = threadIdx.x;
    #pragma unroll
    for (int o = 16; o > 0; o >>= 1) {
        a += __shfl_down_sync(0xffffffffu, a, o);
        b += __shfl_down_sync(0xffffffffu, b, o);
    }
    __syncthreads();
    if ((tid & 31) == 0) { int w = tid >> 5; sh[0][w] = a; sh[1][w] = b; }
    __syncthreads();
    float ra = 0.f, rb = 0.f;
    #pragma unroll
    for (int w = 0; w < 8; w++) { ra += sh[0][w]; rb += sh[1][w]; }
    a = ra; b = rb;
}

__device__ __forceinline__ void blockMax2(float& a, float& b) {
    __shared__ float sh[2][8];
    int tid = threadIdx.x;
    #pragma unroll
    for (int o = 16; o > 0; o >>= 1) {
        a = fmaxf(a, __shfl_down_sync(0xffffffffu, a, o));
        b = fmaxf(b, __shfl_down_sync(0xffffffffu, b, o));
    }
    __syncthreads();
    if ((tid & 31) == 0) { int w = tid >> 5; sh[0][w] = a; sh[1][w] = b; }
    __syncthreads();
    float ra = sh[0][0], rb = sh[1][0];
    #pragma unroll
    for (int w = 1; w < 8; w++) { ra = fmaxf(ra, sh[0][w]); rb = fmaxf(rb, sh[1][w]); }
    a = ra; b = rb;
}

__device__ __forceinline__ void blockSum4(float& a, float& b, float& c, float& d) {
    __shared__ float sh[4][8];
    int tid = threadIdx.x;
    #pragma unroll
    for (int o = 16; o > 0; o >>= 1) {
        a += __shfl_down_sync(0xffffffffu, a, o);
        b += __shfl_down_sync(0xffffffffu, b, o);
        c += __shfl_down_sync(0xffffffffu, c, o);
        d += __shfl_down_sync(0xffffffffu, d, o);
    }
    __syncthreads();
    if ((tid & 31) == 0) { int w = tid >> 5; sh[0][w] = a; sh[1][w] = b; sh[2][w] = c; sh[3][w] = d; }
    __syncthreads();
    float ra = 0.f, rb = 0.f, rc = 0.f, rd = 0.f;
    #pragma unroll
    for (int w = 0; w < 8; w++) { ra += sh[0][w]; rb += sh[1][w]; rc += sh[2][w]; rd += sh[3][w]; }
    a = ra; b = rb; c = rc; d = rd;
}

__global__ void __launch_bounds__(256, 4)
cca_fused_kernel(const float* __restrict__ img,
                 const float* __restrict__ txt,
                 const float* __restrict__ cl,
                 const float* __restrict__ cis,
                 const int*   __restrict__ mc,
                 float* __restrict__ out) {
    __shared__ unsigned sbits[NW * BB];   // TRANSPOSED: [word][row]
    __shared__ int      scnt[BB];
    __shared__ float    scis[BB];

    const int b   = blockIdx.x;    // 0..511
    const int tid = threadIdx.x;   // 0..255

    // ================= phase 1: concept BCE + bitmasks + CLIP rows =================
    {
        int   m    = mc[(size_t)b * CC + tid];
        float x    = cl[(size_t)b * CC + tid];
        float mask = (m != -1) ? 1.f : 0.f;
        float tgt  = (m > 0)   ? 1.f : 0.f;
        float la   = (x > 0.f) ? (x + log1pf(__expf(-x))) : log1pf(__expf(x));
        float loss = (la - x * tgt) * mask;

        unsigned ball = __ballot_sync(0xffffffffu, m > 0);
        if ((tid & 31) == 0) g_bits[b * NW + (tid >> 5)] = ball;

        float ls = loss, ms = mask, pc = tgt;
        blockSum3(ls, ms, pc);
        if (tid == 0) { g_ccl[b] = ls; g_ccl[BB + b] = ms; g_cnt[b] = (int)pc; }
    }
    {
        const float* ri = img + (size_t)b * BB;
        const float* rt = txt + (size_t)b * BB;
        float i0 = ri[tid], i1 = ri[tid + 256];
        float t0 = rt[tid], t1 = rt[tid + 256];
        float mi = fmaxf(i0, i1), mt = fmaxf(t0, t1);
        blockMax2(mi, mt);
        float si = __expf(i0 - mi) + __expf(i1 - mi);
        float st = __expf(t0 - mt) + __expf(t1 - mt);
        blockSum2(si, st);
        if (tid == 0) {
            g_clip[b]      = mi + logf(si) - ri[b];
            g_clip[BB + b] = mt + logf(st) - rt[b];
        }
    }

    // -------- grid barrier 1: RED arrival + volatile poll --------
    __syncthreads();
    if (tid == 0) {
        __threadfence();
        atomicAdd(&g_count, 1u);                     // result unused -> RED
        volatile unsigned* p = &g_count;
        while (*p < GRID) {}
        __threadfence();
    }
    __syncthreads();

    // ================= phase 2: Jaccard -> softmax targets -> KL per row =================
    {
        for (int i = tid; i < BB * NW; i += 256) {
            int row = i >> 3, w = i & (NW - 1);
            sbits[w * BB + row] = g_bits[i];
        }
        for (int i = tid; i < BB; i += 256) scnt[i] = g_cnt[i];
        float maxc = -3.402823e38f, dummy = -3.402823e38f;
        for (int i = tid; i < BB; i += 256) {
            float v = cis[(size_t)b * BB + i];
            scis[i] = v;
            maxc = fmaxf(maxc, v);
        }
        blockMax2(maxc, dummy);   // syncthreads inside also publishes shared fills

        unsigned a[NW];
        #pragma unroll
        for (int w = 0; w < NW; w++) a[w] = sbits[w * BB + b];
        int   cnti = scnt[b];
        float maxs = (cnti > 0) ? TEMP_INV : 0.f;   // sim(i,i)=1 when row nonempty

        float es = 0.f, num = 0.f, ec = 0.f;
        #pragma unroll
        for (int jj = 0; jj < 2; jj++) {
            int j = tid + jj * 256;
            int inter = 0;
            #pragma unroll
            for (int w = 0; w < NW; w++)
                inter += __popc(a[w] & sbits[w * BB + j]);
            int   uni = cnti + scnt[j] - inter;
            float sim = (uni > 0) ? (float)inter / (float)uni : 0.f;
            float s   = sim * TEMP_INV;
            float cij = scis[j];
            float e   = __expf(s - maxs);
            es  += e;
            num += e * (s - cij);
            ec  += __expf(cij - maxc);
        }
        blockSum3(es, ec, num);
        if (tid == 0)
            g_kl[b] = num / es - maxs - logf(es) + maxc + logf(ec);
    }

    // -------- barrier 2 + final combine (block 0) --------
    if (b != 0) {
        __syncthreads();
        if (tid == 0) { __threadfence(); atomicAdd(&g_fin, 1u); }  // RED
        return;
    }
    __syncthreads();
    if (tid == 0) {
        volatile unsigned* p = &g_fin;
        while (*p < GRID - 1) {}
        __threadfence();
    }
    __syncthreads();

    {
        float cs = 0.f, ls = 0.f, ms = 0.f, ks = 0.f;
        for (int i = tid; i < 2 * BB; i += 256) cs += g_clip[i];
        for (int i = tid; i < BB; i += 256) {
            ls += g_ccl[i];
            ms += g_ccl[BB + i];
            ks += g_kl[i];
        }
        blockSum4(cs, ls, ms, ks);
        if (tid == 0) {
            float clip_loss = cs / (2.f * BB);
            float bce_loss  = ls / (ms + 1e-8f);
            float kl_loss   = ks / (float)BB;
            out[0] = clip_loss + 0.5f * bce_loss + 0.3f * kl_loss;
            // reset counters for next graph replay (all other blocks already exited both barriers)
            g_count = 0;
            g_fin   = 0;
            __threadfence();
        }
    }
}

extern "C" void kernel_launch(void* const* d_in, const int* in_sizes, int n_in,
                              void* d_out, int out_size) {
    const float* img = (const float*)d_in[0];   // logits_per_image [512,512]
    const float* txt = (const float*)d_in[1];   // logits_per_text  [512,512]
    const float* cl  = (const float*)d_in[2];   // concepts_logits  [512,256]
    const float* cis = (const float*)d_in[3];   // concepts_image_similarity [512,512]
    const int*   mc  = (const int*)d_in[4];     // medical_concepts [512,256]
    float* out = (float*)d_out;

    cca_fused_kernel<<<GRID, 256>>>(img, txt, cl, cis, mc, out);
}

// round 6
// speedup vs baseline: 1.7084x; 1.7084x over previous
#include <cuda_runtime.h>
#include <math.h>

#define BB 512
#define CC 256
#define NW 8                 // 256 concepts / 32 bits
#define TEMP_INV (1.0f/0.07f)
#define GRID 512

// ---- persistent scratch (no allocation allowed) ----
__device__ float    g_clip[2*BB];    // per-row (lse - diag): img [0..511], txt [512..1023]
__device__ float    g_ccl [2*BB];    // per-row bce sum [0..511], mask sum [512..1023]
__device__ float    g_kl  [BB];      // per-row KL term
__device__ unsigned g_bits[BB*NW];   // binary concept bitmasks (row-major [row][word])
__device__ int      g_cnt [BB];      // per-row positive-concept popcount
__device__ float    g_scalars[3];    // clip_sum, bce_sum, mask_sum
__device__ unsigned g_done1 = 0;     // K1 completion counter (atomicInc wraps -> self-reset)
__device__ unsigned g_done2 = 0;     // K2 completion counter

// ---------- deterministic fused block reductions (256 threads) ----------
__device__ __forceinline__ void blockSum3(float& a, float& b, float& c) {
    __shared__ float sh[3][8];
    int tid = threadIdx.x;
    #pragma unroll
    for (int o = 16; o > 0; o >>= 1) {
        a += __shfl_down_sync(0xffffffffu, a, o);
        b += __shfl_down_sync(0xffffffffu, b, o);
        c += __shfl_down_sync(0xffffffffu, c, o);
    }
    __syncthreads();
    if ((tid & 31) == 0) { int w = tid >> 5; sh[0][w] = a; sh[1][w] = b; sh[2][w] = c; }
    __syncthreads();
    float ra = 0.f, rb = 0.f, rc = 0.f;
    #pragma unroll
    for (int w = 0; w < 8; w++) { ra += sh[0][w]; rb += sh[1][w]; rc += sh[2][w]; }
    a = ra; b = rb; c = rc;
    __syncthreads();
}

__device__ __forceinline__ void blockSum2(float& a, float& b) {
    __shared__ float sh[2][8];
    int tid = threadIdx.x;
    #pragma unroll
    for (int o = 16; o > 0; o >>= 1) {
        a += __shfl_down_sync(0xffffffffu, a, o);
        b += __shfl_down_sync(0xffffffffu, b, o);
    }
    __syncthreads();
    if ((tid & 31) == 0) { int w = tid >> 5; sh[0][w] = a; sh[1][w] = b; }
    __syncthreads();
    float ra = 0.f, rb = 0.f;
    #pragma unroll
    for (int w = 0; w < 8; w++) { ra += sh[0][w]; rb += sh[1][w]; }
    a = ra; b = rb;
    __syncthreads();
}

__device__ __forceinline__ void blockMax2(float& a, float& b) {
    __shared__ float sh[2][8];
    int tid = threadIdx.x;
    #pragma unroll
    for (int o = 16; o > 0; o >>= 1) {
        a = fmaxf(a, __shfl_down_sync(0xffffffffu, a, o));
        b = fmaxf(b, __shfl_down_sync(0xffffffffu, b, o));
    }
    __syncthreads();
    if ((tid & 31) == 0) { int w = tid >> 5; sh[0][w] = a; sh[1][w] = b; }
    __syncthreads();
    float ra = sh[0][0], rb = sh[1][0];
    #pragma unroll
    for (int w = 1; w < 8; w++) { ra = fmaxf(ra, sh[0][w]); rb = fmaxf(rb, sh[1][w]); }
    a = ra; b = rb;
    __syncthreads();
}

// =======================================================================
// K1: per-row BCE + bitmasks + CLIP lse; last block folds partials -> scalars
// =======================================================================
__global__ void __launch_bounds__(256, 4)
k1_rows(const float* __restrict__ img,
        const float* __restrict__ txt,
        const float* __restrict__ cl,
        const int*   __restrict__ mc) {
    const int b   = blockIdx.x;
    const int tid = threadIdx.x;

    // concept BCE + bitmask
    {
        int   m    = mc[(size_t)b * CC + tid];
        float x    = cl[(size_t)b * CC + tid];
        float mask = (m != -1) ? 1.f : 0.f;
        float tgt  = (m > 0)   ? 1.f : 0.f;
        float la   = (x > 0.f) ? (x + log1pf(__expf(-x))) : log1pf(__expf(x));
        float loss = (la - x * tgt) * mask;

        unsigned ball = __ballot_sync(0xffffffffu, m > 0);
        if ((tid & 31) == 0) g_bits[b * NW + (tid >> 5)] = ball;

        float ls = loss, ms = mask, pc = tgt;
        blockSum3(ls, ms, pc);
        if (tid == 0) { g_ccl[b] = ls; g_ccl[BB + b] = ms; g_cnt[b] = (int)pc; }
    }
    // CLIP rows (image + text together)
    {
        const float* ri = img + (size_t)b * BB;
        const float* rt = txt + (size_t)b * BB;
        float i0 = ri[tid], i1 = ri[tid + 256];
        float t0 = rt[tid], t1 = rt[tid + 256];
        float mi = fmaxf(i0, i1), mt = fmaxf(t0, t1);
        blockMax2(mi, mt);
        float si = __expf(i0 - mi) + __expf(i1 - mi);
        float st = __expf(t0 - mt) + __expf(t1 - mt);
        blockSum2(si, st);
        if (tid == 0) {
            g_clip[b]      = mi + logf(si) - ri[b];
            g_clip[BB + b] = mt + logf(st) - rt[b];
        }
    }

    // last-arriving block folds per-row partials (no spinning)
    __shared__ bool is_last;
    __syncthreads();
    if (tid == 0) {
        __threadfence();
        unsigned t = atomicInc(&g_done1, GRID - 1);   // wraps to 0 -> replay-safe
        is_last = (t == GRID - 1);
    }
    __syncthreads();
    if (is_last) {
        __threadfence();   // acquire ordering for other blocks' writes
        float cs = 0.f, ls = 0.f, ms = 0.f;
        #pragma unroll
        for (int k = 0; k < 4; k++) cs += __ldcg(&g_clip[tid + k * 256]);
        #pragma unroll
        for (int k = 0; k < 2; k++) {
            ls += __ldcg(&g_ccl[tid + k * 256]);
            ms += __ldcg(&g_ccl[BB + tid + k * 256]);
        }
        blockSum3(cs, ls, ms);
        if (tid == 0) { g_scalars[0] = cs; g_scalars[1] = ls; g_scalars[2] = ms; }
    }
}

// =======================================================================
// K2: Jaccard -> softmax targets -> KL per row; last block combines -> out
// =======================================================================
__global__ void __launch_bounds__(256, 4)
k2_kl(const float* __restrict__ cis, float* __restrict__ out) {
    __shared__ unsigned sbits[NW * BB];   // transposed: [word][row], conflict-free inner loop
    __shared__ int      scnt[BB];
    __shared__ float    scis[BB];

    const int b   = blockIdx.x;
    const int tid = threadIdx.x;

    // fill smem: 128-bit loads of the bit table, transposed store
    {
        const uint4* bits4 = (const uint4*)g_bits;
        #pragma unroll
        for (int k = 0; k < 4; k++) {
            int i = tid + k * 256;            // 0..1023
            uint4 v = bits4[i];               // row = i>>1, words (i&1)*4 ..+3
            int row = i >> 1, w0 = (i & 1) * 4;
            sbits[(w0 + 0) * BB + row] = v.x;
            sbits[(w0 + 1) * BB + row] = v.y;
            sbits[(w0 + 2) * BB + row] = v.z;
            sbits[(w0 + 3) * BB + row] = v.w;
        }
        #pragma unroll
        for (int k = 0; k < 2; k++) scnt[tid + k * 256] = g_cnt[tid + k * 256];
    }
    float maxc = -3.402823e38f, dummy = -3.402823e38f;
    #pragma unroll
    for (int k = 0; k < 2; k++) {
        float v = cis[(size_t)b * BB + tid + k * 256];
        scis[tid + k * 256] = v;
        maxc = fmaxf(maxc, v);
    }
    blockMax2(maxc, dummy);   // internal syncthreads publishes smem fills

    unsigned a[NW];
    #pragma unroll
    for (int w = 0; w < NW; w++) a[w] = sbits[w * BB + b];
    int   cnti = scnt[b];
    float maxs = (cnti > 0) ? TEMP_INV : 0.f;   // sim(i,i)=1 when row nonempty

    float es = 0.f, num = 0.f, ec = 0.f;
    #pragma unroll
    for (int jj = 0; jj < 2; jj++) {
        int j = tid + jj * 256;
        int inter = 0;
        #pragma unroll
        for (int w = 0; w < NW; w++)
            inter += __popc(a[w] & sbits[w * BB + j]);
        int   uni = cnti + scnt[j] - inter;
        float sim = (uni > 0) ? (float)inter / (float)uni : 0.f;
        float s   = sim * TEMP_INV;
        float cij = scis[j];
        float e   = __expf(s - maxs);
        es  += e;
        num += e * (s - cij);
        ec  += __expf(cij - maxc);
    }
    blockSum3(es, ec, num);
    if (tid == 0)
        g_kl[b] = num / es - maxs - logf(es) + maxc + logf(ec);

    // last-arriving block combines everything (no spinning)
    __shared__ bool is_last;
    __syncthreads();
    if (tid == 0) {
        __threadfence();
        unsigned t = atomicInc(&g_done2, GRID - 1);
        is_last = (t == GRID - 1);
    }
    __syncthreads();
    if (is_last) {
        __threadfence();
        float ks = 0.f, d1 = 0.f, d2 = 0.f;
        #pragma unroll
        for (int k = 0; k < 2; k++) ks += __ldcg(&g_kl[tid + k * 256]);
        blockSum3(ks, d1, d2);
        if (tid == 0) {
            float clip_loss = __ldcg(&g_scalars[0]) / (2.f * BB);
            float bce_loss  = __ldcg(&g_scalars[1]) / (__ldcg(&g_scalars[2]) + 1e-8f);
            float kl_loss   = ks / (float)BB;
            out[0] = clip_loss + 0.5f * bce_loss + 0.3f * kl_loss;
        }
    }
}

extern "C" void kernel_launch(void* const* d_in, const int* in_sizes, int n_in,
                              void* d_out, int out_size) {
    const float* img = (const float*)d_in[0];   // logits_per_image [512,512]
    const float* txt = (const float*)d_in[1];   // logits_per_text  [512,512]
    const float* cl  = (const float*)d_in[2];   // concepts_logits  [512,256]
    const float* cis = (const float*)d_in[3];   // concepts_image_similarity [512,512]
    const int*   mc  = (const int*)d_in[4];     // medical_concepts [512,256]
    float* out = (float*)d_out;

    k1_rows<<<GRID, 256>>>(img, txt, cl, mc);
    k2_kl  <<<GRID, 256>>>(cis, out);
}

// round 7
// speedup vs baseline: 1.7346x; 1.0154x over previous
#include <cuda_runtime.h>
#include <math.h>

#define BB 512
#define CC 256
#define NW 8                 // 256 concepts / 32 bits
#define TEMP_INV (1.0f/0.07f)
#define GRID 512

// ---- persistent scratch (no allocation allowed) ----
__device__ float    g_clip[2*BB];    // per-row (lse - diag): img [0..511], txt [512..1023]
__device__ float    g_ccl [2*BB];    // per-row bce sum [0..511], mask sum [512..1023]
__device__ float    g_kl  [BB];      // per-row KL term
__device__ unsigned g_bits[BB*NW];   // binary concept bitmasks (row-major [row][word])
__device__ int      g_cnt [BB];      // per-row positive-concept popcount
__device__ float    g_scalars[3];    // clip_sum, bce_sum, mask_sum
__device__ unsigned g_done1 = 0;     // K1 completion counter (atomicInc wraps -> self-reset)
__device__ unsigned g_done2 = 0;     // K2 completion counter

// ---------- deterministic block reductions (256 threads), no trailing sync ----------
__device__ __forceinline__ void blockMax2(float& a, float& b) {
    __shared__ float sh[2][8];
    int tid = threadIdx.x;
    #pragma unroll
    for (int o = 16; o > 0; o >>= 1) {
        a = fmaxf(a, __shfl_down_sync(0xffffffffu, a, o));
        b = fmaxf(b, __shfl_down_sync(0xffffffffu, b, o));
    }
    if ((tid & 31) == 0) { int w = tid >> 5; sh[0][w] = a; sh[1][w] = b; }
    __syncthreads();
    float ra = sh[0][0], rb = sh[1][0];
    #pragma unroll
    for (int w = 1; w < 8; w++) { ra = fmaxf(ra, sh[0][w]); rb = fmaxf(rb, sh[1][w]); }
    a = ra; b = rb;
}

__device__ __forceinline__ float blockMax1(float a) {
    __shared__ float sh[8];
    int tid = threadIdx.x;
    #pragma unroll
    for (int o = 16; o > 0; o >>= 1)
        a = fmaxf(a, __shfl_down_sync(0xffffffffu, a, o));
    if ((tid & 31) == 0) sh[tid >> 5] = a;
    __syncthreads();
    float ra = sh[0];
    #pragma unroll
    for (int w = 1; w < 8; w++) ra = fmaxf(ra, sh[w]);
    return ra;
}

__device__ __forceinline__ void blockSum3(float& a, float& b, float& c) {
    __shared__ float sh[3][8];
    int tid = threadIdx.x;
    #pragma unroll
    for (int o = 16; o > 0; o >>= 1) {
        a += __shfl_down_sync(0xffffffffu, a, o);
        b += __shfl_down_sync(0xffffffffu, b, o);
        c += __shfl_down_sync(0xffffffffu, c, o);
    }
    if ((tid & 31) == 0) { int w = tid >> 5; sh[0][w] = a; sh[1][w] = b; sh[2][w] = c; }
    __syncthreads();
    float ra = 0.f, rb = 0.f, rc = 0.f;
    #pragma unroll
    for (int w = 0; w < 8; w++) { ra += sh[0][w]; rb += sh[1][w]; rc += sh[2][w]; }
    a = ra; b = rb; c = rc;
}

__device__ __forceinline__ void blockSum5(float& a, float& b, float& c, float& d, float& e) {
    __shared__ float sh[5][8];
    int tid = threadIdx.x;
    #pragma unroll
    for (int o = 16; o > 0; o >>= 1) {
        a += __shfl_down_sync(0xffffffffu, a, o);
        b += __shfl_down_sync(0xffffffffu, b, o);
        c += __shfl_down_sync(0xffffffffu, c, o);
        d += __shfl_down_sync(0xffffffffu, d, o);
        e += __shfl_down_sync(0xffffffffu, e, o);
    }
    if ((tid & 31) == 0) {
        int w = tid >> 5;
        sh[0][w] = a; sh[1][w] = b; sh[2][w] = c; sh[3][w] = d; sh[4][w] = e;
    }
    __syncthreads();
    float ra = 0.f, rb = 0.f, rc = 0.f, rd = 0.f, re = 0.f;
    #pragma unroll
    for (int w = 0; w < 8; w++) {
        ra += sh[0][w]; rb += sh[1][w]; rc += sh[2][w]; rd += sh[3][w]; re += sh[4][w];
    }
    a = ra; b = rb; c = rc; d = rd; e = re;
}

// =======================================================================
// K1: per-row BCE + bitmasks + CLIP lse (img+txt); last block folds -> scalars
// =======================================================================
__global__ void __launch_bounds__(256, 4)
k1_rows(const float* __restrict__ img,
        const float* __restrict__ txt,
        const float* __restrict__ cl,
        const int*   __restrict__ mc) {
    const int b   = blockIdx.x;
    const int tid = threadIdx.x;

    // ---- issue all global loads up front ----
    int   m  = mc[(size_t)b * CC + tid];
    float x  = cl[(size_t)b * CC + tid];
    const float* ri = img + (size_t)b * BB;
    const float* rt = txt + (size_t)b * BB;
    float i0 = ri[tid], i1 = ri[tid + 256];
    float t0 = rt[tid], t1 = rt[tid + 256];

    // BCE terms + bitmask
    float mask = (m != -1) ? 1.f : 0.f;
    float tgt  = (m > 0)   ? 1.f : 0.f;
    float la   = (x > 0.f) ? (x + log1pf(__expf(-x))) : log1pf(__expf(x));
    float loss = (la - x * tgt) * mask;
    unsigned ball = __ballot_sync(0xffffffffu, m > 0);
    if ((tid & 31) == 0) g_bits[b * NW + (tid >> 5)] = ball;

    // one max round + one fused 5-sum round
    float mi = fmaxf(i0, i1), mt = fmaxf(t0, t1);
    blockMax2(mi, mt);
    float si = __expf(i0 - mi) + __expf(i1 - mi);
    float st = __expf(t0 - mt) + __expf(t1 - mt);
    float ls = loss, ms = mask, pc = tgt;
    __syncthreads();                    // protect blockMax2's smem before blockSum5 reuse pattern
    blockSum5(si, st, ls, ms, pc);
    if (tid == 0) {
        g_clip[b]      = mi + logf(si) - ri[b];
        g_clip[BB + b] = mt + logf(st) - rt[b];
        g_ccl[b]       = ls;
        g_ccl[BB + b]  = ms;
        g_cnt[b]       = (int)pc;
    }

    // last-arriving block folds per-row partials (no spinning)
    __shared__ bool is_last;
    __syncthreads();
    if (tid == 0) {
        __threadfence();
        unsigned t = atomicInc(&g_done1, GRID - 1);   // wraps to 0 -> replay-safe
        is_last = (t == GRID - 1);
    }
    __syncthreads();
    if (is_last) {
        __threadfence();
        float cs = 0.f, l2 = 0.f, m2 = 0.f;
        #pragma unroll
        for (int k = 0; k < 4; k++) cs += __ldcg(&g_clip[tid + k * 256]);
        #pragma unroll
        for (int k = 0; k < 2; k++) {
            l2 += __ldcg(&g_ccl[tid + k * 256]);
            m2 += __ldcg(&g_ccl[BB + tid + k * 256]);
        }
        blockSum3(cs, l2, m2);
        if (tid == 0) { g_scalars[0] = cs; g_scalars[1] = l2; g_scalars[2] = m2; }
    }
}

// =======================================================================
// K2: Jaccard -> KL per row, register-only (no smem tile); last block -> out
// =======================================================================
__global__ void __launch_bounds__(256, 4)
k2_kl(const float* __restrict__ cis, float* __restrict__ out) {
    const int b   = blockIdx.x;
    const int tid = threadIdx.x;
    const uint4* bits4 = (const uint4*)g_bits;   // 2 uint4 per row

    // own row's mask (broadcast loads) + count
    uint4 a0 = bits4[2 * b], a1 = bits4[2 * b + 1];
    int   cnti = g_cnt[b];

    // cis values for this thread's two columns
    float c0 = cis[(size_t)b * BB + tid];
    float c1 = cis[(size_t)b * BB + tid + 256];

    // this thread's two j bit-rows + counts (issue early)
    uint4 p0 = bits4[2 * tid],         p1 = bits4[2 * tid + 1];
    uint4 q0 = bits4[2 * (tid + 256)], q1 = bits4[2 * (tid + 256) + 1];
    int   cj0 = g_cnt[tid], cj1 = g_cnt[tid + 256];

    float maxc = blockMax1(fmaxf(c0, c1));
    float maxs = (cnti > 0) ? TEMP_INV : 0.f;   // sim(i,i)=1 when row nonempty

    float es = 0.f, num = 0.f, ec = 0.f;
    {
        int inter = __popc(a0.x & p0.x) + __popc(a0.y & p0.y)
                  + __popc(a0.z & p0.z) + __popc(a0.w & p0.w)
                  + __popc(a1.x & p1.x) + __popc(a1.y & p1.y)
                  + __popc(a1.z & p1.z) + __popc(a1.w & p1.w);
        int   uni = cnti + cj0 - inter;
        float sim = (uni > 0) ? (float)inter / (float)uni : 0.f;
        float s   = sim * TEMP_INV;
        float e   = __expf(s - maxs);
        es  += e;
        num += e * (s - c0);
        ec  += __expf(c0 - maxc);
    }
    {
        int inter = __popc(a0.x & q0.x) + __popc(a0.y & q0.y)
                  + __popc(a0.z & q0.z) + __popc(a0.w & q0.w)
                  + __popc(a1.x & q1.x) + __popc(a1.y & q1.y)
                  + __popc(a1.z & q1.z) + __popc(a1.w & q1.w);
        int   uni = cnti + cj1 - inter;
        float sim = (uni > 0) ? (float)inter / (float)uni : 0.f;
        float s   = sim * TEMP_INV;
        float e   = __expf(s - maxs);
        es  += e;
        num += e * (s - c1);
        ec  += __expf(c1 - maxc);
    }
    __syncthreads();                  // protect blockMax1's smem before blockSum3
    blockSum3(es, ec, num);
    if (tid == 0)
        g_kl[b] = num / es - maxs - logf(es) + maxc + logf(ec);

    // last-arriving block combines everything (no spinning)
    __shared__ bool is_last;
    __syncthreads();
    if (tid == 0) {
        __threadfence();
        unsigned t = atomicInc(&g_done2, GRID - 1);
        is_last = (t == GRID - 1);
    }
    __syncthreads();
    if (is_last) {
        __threadfence();
        float ks = 0.f, d1 = 0.f, d2 = 0.f;
        #pragma unroll
        for (int k = 0; k < 2; k++) ks += __ldcg(&g_kl[tid + k * 256]);
        blockSum3(ks, d1, d2);
        if (tid == 0) {
            float clip_loss = __ldcg(&g_scalars[0]) / (2.f * BB);
            float bce_loss  = __ldcg(&g_scalars[1]) / (__ldcg(&g_scalars[2]) + 1e-8f);
            float kl_loss   = ks / (float)BB;
            out[0] = clip_loss + 0.5f * bce_loss + 0.3f * kl_loss;
        }
    }
}

extern "C" void kernel_launch(void* const* d_in, const int* in_sizes, int n_in,
                              void* d_out, int out_size) {
    const float* img = (const float*)d_in[0];   // logits_per_image [512,512]
    const float* txt = (const float*)d_in[1];   // logits_per_text  [512,512]
    const float* cl  = (const float*)d_in[2];   // concepts_logits  [512,256]
    const float* cis = (const float*)d_in[3];   // concepts_image_similarity [512,512]
    const int*   mc  = (const int*)d_in[4];     // medical_concepts [512,256]
    float* out = (float*)d_out;

    k1_rows<<<GRID, 256>>>(img, txt, cl, mc);
    k2_kl  <<<GRID, 256>>>(cis, out);
}

// round 8
// speedup vs baseline: 1.9775x; 1.1400x over previous
#include <cuda_runtime.h>
#include <math.h>

#define BB 512
#define CC 256
#define NW 8                 // 256 concepts / 32 bits
#define TEMP_INV (1.0f/0.07f)
#define GRID 512
#define NGRP 32              // first-level counter groups (16 blocks each)

// ---- persistent scratch (no allocation allowed) ----
__device__ float    g_clip[2*BB];    // per-row (lse - diag): img [0..511], txt [512..1023]
__device__ float    g_ccl [2*BB];    // per-row bce sum [0..511], mask sum [512..1023]
__device__ float    g_kl  [BB];      // per-row KL term
__device__ unsigned g_bits[BB*NW];   // binary concept bitmasks (row-major [row][word])
__device__ int      g_cnt [BB];      // per-row positive-concept popcount
__device__ unsigned g_doneA[NGRP];   // first-level completion counters (atomicInc wrap -> self-reset)
__device__ unsigned g_doneB = 0;     // second-level counter

// ---------- deterministic block reductions (256 threads) ----------
__device__ __forceinline__ void blockMax2(float& a, float& b) {
    __shared__ float sh[2][8];
    int tid = threadIdx.x;
    #pragma unroll
    for (int o = 16; o > 0; o >>= 1) {
        a = fmaxf(a, __shfl_down_sync(0xffffffffu, a, o));
        b = fmaxf(b, __shfl_down_sync(0xffffffffu, b, o));
    }
    if ((tid & 31) == 0) { int w = tid >> 5; sh[0][w] = a; sh[1][w] = b; }
    __syncthreads();
    float ra = sh[0][0], rb = sh[1][0];
    #pragma unroll
    for (int w = 1; w < 8; w++) { ra = fmaxf(ra, sh[0][w]); rb = fmaxf(rb, sh[1][w]); }
    a = ra; b = rb;
}

__device__ __forceinline__ float blockMax1(float a) {
    __shared__ float sh[8];
    int tid = threadIdx.x;
    #pragma unroll
    for (int o = 16; o > 0; o >>= 1)
        a = fmaxf(a, __shfl_down_sync(0xffffffffu, a, o));
    if ((tid & 31) == 0) sh[tid >> 5] = a;
    __syncthreads();
    float ra = sh[0];
    #pragma unroll
    for (int w = 1; w < 8; w++) ra = fmaxf(ra, sh[w]);
    return ra;
}

__device__ __forceinline__ void blockSum3(float& a, float& b, float& c) {
    __shared__ float sh[3][8];
    int tid = threadIdx.x;
    #pragma unroll
    for (int o = 16; o > 0; o >>= 1) {
        a += __shfl_down_sync(0xffffffffu, a, o);
        b += __shfl_down_sync(0xffffffffu, b, o);
        c += __shfl_down_sync(0xffffffffu, c, o);
    }
    if ((tid & 31) == 0) { int w = tid >> 5; sh[0][w] = a; sh[1][w] = b; sh[2][w] = c; }
    __syncthreads();
    float ra = 0.f, rb = 0.f, rc = 0.f;
    #pragma unroll
    for (int w = 0; w < 8; w++) { ra += sh[0][w]; rb += sh[1][w]; rc += sh[2][w]; }
    a = ra; b = rb; c = rc;
}

__device__ __forceinline__ void blockSum4(float& a, float& b, float& c, float& d) {
    __shared__ float sh[4][8];
    int tid = threadIdx.x;
    #pragma unroll
    for (int o = 16; o > 0; o >>= 1) {
        a += __shfl_down_sync(0xffffffffu, a, o);
        b += __shfl_down_sync(0xffffffffu, b, o);
        c += __shfl_down_sync(0xffffffffu, c, o);
        d += __shfl_down_sync(0xffffffffu, d, o);
    }
    if ((tid & 31) == 0) { int w = tid >> 5; sh[0][w] = a; sh[1][w] = b; sh[2][w] = c; sh[3][w] = d; }
    __syncthreads();
    float ra = 0.f, rb = 0.f, rc = 0.f, rd = 0.f;
    #pragma unroll
    for (int w = 0; w < 8; w++) { ra += sh[0][w]; rb += sh[1][w]; rc += sh[2][w]; rd += sh[3][w]; }
    a = ra; b = rb; c = rc; d = rd;
}

__device__ __forceinline__ void blockSum5(float& a, float& b, float& c, float& d, float& e) {
    __shared__ float sh[5][8];
    int tid = threadIdx.x;
    #pragma unroll
    for (int o = 16; o > 0; o >>= 1) {
        a += __shfl_down_sync(0xffffffffu, a, o);
        b += __shfl_down_sync(0xffffffffu, b, o);
        c += __shfl_down_sync(0xffffffffu, c, o);
        d += __shfl_down_sync(0xffffffffu, d, o);
        e += __shfl_down_sync(0xffffffffu, e, o);
    }
    if ((tid & 31) == 0) {
        int w = tid >> 5;
        sh[0][w] = a; sh[1][w] = b; sh[2][w] = c; sh[3][w] = d; sh[4][w] = e;
    }
    __syncthreads();
    float ra = 0.f, rb = 0.f, rc = 0.f, rd = 0.f, re = 0.f;
    #pragma unroll
    for (int w = 0; w < 8; w++) {
        ra += sh[0][w]; rb += sh[1][w]; rc += sh[2][w]; rd += sh[3][w]; re += sh[4][w];
    }
    a = ra; b = rb; c = rc; d = rd; e = re;
}

// =======================================================================
// K1: per-row BCE + bitmasks + CLIP lse (img+txt). NO atomics, no fold.
// =======================================================================
__global__ void __launch_bounds__(256, 4)
k1_rows(const float* __restrict__ img,
        const float* __restrict__ txt,
        const float* __restrict__ cl,
        const int*   __restrict__ mc) {
    const int b   = blockIdx.x;
    const int tid = threadIdx.x;

    // issue all global loads up front
    int   m  = mc[(size_t)b * CC + tid];
    float x  = cl[(size_t)b * CC + tid];
    const float* ri = img + (size_t)b * BB;
    const float* rt = txt + (size_t)b * BB;
    float i0 = ri[tid], i1 = ri[tid + 256];
    float t0 = rt[tid], t1 = rt[tid + 256];

    // BCE terms + bitmask
    float mask = (m != -1) ? 1.f : 0.f;
    float tgt  = (m > 0)   ? 1.f : 0.f;
    float la   = (x > 0.f) ? (x + log1pf(__expf(-x))) : log1pf(__expf(x));
    float loss = (la - x * tgt) * mask;
    unsigned ball = __ballot_sync(0xffffffffu, m > 0);
    if ((tid & 31) == 0) g_bits[b * NW + (tid >> 5)] = ball;

    // one max round + one fused 5-sum round (distinct static smem arrays)
    float mi = fmaxf(i0, i1), mt = fmaxf(t0, t1);
    blockMax2(mi, mt);
    float si = __expf(i0 - mi) + __expf(i1 - mi);
    float st = __expf(t0 - mt) + __expf(t1 - mt);
    float ls = loss, ms = mask, pc = tgt;
    blockSum5(si, st, ls, ms, pc);
    if (tid == 0) {
        g_clip[b]      = mi + logf(si) - ri[b];
        g_clip[BB + b] = mt + logf(st) - rt[b];
        g_ccl[b]       = ls;
        g_ccl[BB + b]  = ms;
        g_cnt[b]       = (int)pc;
    }
}

// =======================================================================
// K2: Jaccard -> KL per row (register-only); tree-counter last block -> out
// =======================================================================
__global__ void __launch_bounds__(256, 4)
k2_kl(const float* __restrict__ cis, float* __restrict__ out) {
    const int b   = blockIdx.x;
    const int tid = threadIdx.x;
    const uint4* bits4 = (const uint4*)g_bits;   // 2 uint4 per row

    // own row's mask (broadcast loads) + count
    uint4 a0 = bits4[2 * b], a1 = bits4[2 * b + 1];
    int   cnti = g_cnt[b];

    // cis values for this thread's two columns
    float c0 = cis[(size_t)b * BB + tid];
    float c1 = cis[(size_t)b * BB + tid + 256];

    // this thread's two j bit-rows + counts (issue early)
    uint4 p0 = bits4[2 * tid],         p1 = bits4[2 * tid + 1];
    uint4 q0 = bits4[2 * (tid + 256)], q1 = bits4[2 * (tid + 256) + 1];
    int   cj0 = g_cnt[tid], cj1 = g_cnt[tid + 256];

    float maxc = blockMax1(fmaxf(c0, c1));
    float maxs = (cnti > 0) ? TEMP_INV : 0.f;   // sim(i,i)=1 when row nonempty

    float es = 0.f, num = 0.f, ec = 0.f;
    {
        int inter = __popc(a0.x & p0.x) + __popc(a0.y & p0.y)
                  + __popc(a0.z & p0.z) + __popc(a0.w & p0.w)
                  + __popc(a1.x & p1.x) + __popc(a1.y & p1.y)
                  + __popc(a1.z & p1.z) + __popc(a1.w & p1.w);
        int   uni = cnti + cj0 - inter;
        float sim = (uni > 0) ? (float)inter / (float)uni : 0.f;
        float s   = sim * TEMP_INV;
        float e   = __expf(s - maxs);
        es  += e;
        num += e * (s - c0);
        ec  += __expf(c0 - maxc);
    }
    {
        int inter = __popc(a0.x & q0.x) + __popc(a0.y & q0.y)
                  + __popc(a0.z & q0.z) + __popc(a0.w & q0.w)
                  + __popc(a1.x & q1.x) + __popc(a1.y & q1.y)
                  + __popc(a1.z & q1.z) + __popc(a1.w & q1.w);
        int   uni = cnti + cj1 - inter;
        float sim = (uni > 0) ? (float)inter / (float)uni : 0.f;
        float s   = sim * TEMP_INV;
        float e   = __expf(s - maxs);
        es  += e;
        num += e * (s - c1);
        ec  += __expf(c1 - maxc);
    }
    blockSum3(es, ec, num);
    if (tid == 0)
        g_kl[b] = num / es - maxs - logf(es) + maxc + logf(ec);

    // -------- two-level completion tree (no spinning, low contention) --------
    __shared__ bool is_last;
    __syncthreads();
    if (tid == 0) {
        __threadfence();
        bool grp_last = false;
        unsigned t = atomicInc(&g_doneA[b >> 4], 15u);   // 16 blocks per group, wraps -> replay-safe
        grp_last = (t == 15u);
        is_last = false;
        if (grp_last) {
            unsigned u = atomicInc(&g_doneB, NGRP - 1);  // 32 group arrivals, wraps
            is_last = (u == NGRP - 1);
        }
    }
    __syncthreads();
    if (is_last) {
        __threadfence();   // acquire for all other blocks' g_kl writes
        float cs = 0.f, ls = 0.f, ms = 0.f, ks = 0.f;
        #pragma unroll
        for (int k = 0; k < 4; k++) cs += __ldcg(&g_clip[tid + k * 256]);
        #pragma unroll
        for (int k = 0; k < 2; k++) {
            ls += __ldcg(&g_ccl[tid + k * 256]);
            ms += __ldcg(&g_ccl[BB + tid + k * 256]);
            ks += __ldcg(&g_kl[tid + k * 256]);
        }
        blockSum4(cs, ls, ms, ks);
        if (tid == 0) {
            float clip_loss = cs / (2.f * BB);
            float bce_loss  = ls / (ms + 1e-8f);
            float kl_loss   = ks / (float)BB;
            out[0] = clip_loss + 0.5f * bce_loss + 0.3f * kl_loss;
        }
    }
}

extern "C" void kernel_launch(void* const* d_in, const int* in_sizes, int n_in,
                              void* d_out, int out_size) {
    const float* img = (const float*)d_in[0];   // logits_per_image [512,512]
    const float* txt = (const float*)d_in[1];   // logits_per_text  [512,512]
    const float* cl  = (const float*)d_in[2];   // concepts_logits  [512,256]
    const float* cis = (const float*)d_in[3];   // concepts_image_similarity [512,512]
    const int*   mc  = (const int*)d_in[4];     // medical_concepts [512,256]
    float* out = (float*)d_out;

    k1_rows<<<GRID, 256>>>(img, txt, cl, mc);
    k2_kl  <<<GRID, 256>>>(cis, out);
}